// round 2
// baseline (speedup 1.0000x reference)
#include <cuda_runtime.h>
#include <cfloat>

// Problem constants
#define NB   256     // batch
#define NN   1152    // input capsules
#define DIN  8       // input capsule dim
#define NC   10      // output capsules
#define NU   16      // output capsule dim
#define TPB  512
#define PAD  20      // floats per u_hat row (16 + pad for bank/alignment)

// Shared memory layout (float offsets)
#define UHB        (NN * PAD)           // 23040  (one batch of u_hat)
#define A_OFF      (2 * UHB)            // 46080  agreement logits a[2][NN]
#define CC_OFF     (A_OFF + 2 * NN)     // 48384  unnorm. softmax c[2][NN]
#define RED_OFF    (CC_OFF + 2 * NN)    // 50688  s partials [2][16 warps][16 u]
#define WRED_OFF   (RED_OFF + 512)      // 51200  warp-reduction scratch [2][16]
#define MS_OFF     (WRED_OFF + 32)      // 51232  m0,m1,S0,S1
#define VS_OFF     (MS_OFF + 4)         // 51236  v[2][16]
#define SMEM_FLOATS (VS_OFF + 32)       // 51268  -> 205072 bytes

__global__ __launch_bounds__(TPB, 1)
void caps_routing_kernel(const float* __restrict__ inp,
                         const float* __restrict__ W,
                         float* __restrict__ out)
{
    extern __shared__ float sm[];
    const int t    = threadIdx.x;
    const int lane = t & 31;
    const int warp = t >> 5;
    const int cc   = blockIdx.x;        // output capsule 0..9
    const int b0   = blockIdx.y << 1;   // batch pair

    // ================= Phase 0: u_hat[b0..b0+1][n][u] into SMEM =================
    // thread = (u-quad u4 = t&3, group gg = t>>2). W[c] read ONCE, used for both batches.
    {
        const int u4 = t & 3;
        const int gg = t >> 2;          // 0..127
        const float* Wc = W + (size_t)cc * (NN * DIN * NU);
        for (int k = 0; k < 9; ++k) {
            const int n = gg + (k << 7);
            const float4* ip0 = reinterpret_cast<const float4*>(inp + ((size_t)b0       * NN + n) * DIN);
            const float4* ip1 = reinterpret_cast<const float4*>(inp + ((size_t)(b0 + 1) * NN + n) * DIN);
            float4 x0 = ip0[0], x1 = ip0[1];
            float4 y0 = ip1[0], y1 = ip1[1];
            float in0[8] = {x0.x, x0.y, x0.z, x0.w, x1.x, x1.y, x1.z, x1.w};
            float in1[8] = {y0.x, y0.y, y0.z, y0.w, y1.x, y1.y, y1.z, y1.w};
            const float4* wp = reinterpret_cast<const float4*>(Wc + (size_t)n * (DIN * NU)) + u4;
            float a0 = 0.f, a1 = 0.f, a2 = 0.f, a3 = 0.f;
            float c0 = 0.f, c1 = 0.f, c2 = 0.f, c3 = 0.f;
            #pragma unroll
            for (int i = 0; i < 8; ++i) {
                float4 w = wp[i * 4];   // W[c][n][i][u4*4 .. u4*4+3]
                a0 += in0[i] * w.x;  a1 += in0[i] * w.y;
                a2 += in0[i] * w.z;  a3 += in0[i] * w.w;
                c0 += in1[i] * w.x;  c1 += in1[i] * w.y;
                c2 += in1[i] * w.z;  c3 += in1[i] * w.w;
            }
            *reinterpret_cast<float4*>(&sm[      n * PAD + u4 * 4]) = make_float4(a0, a1, a2, a3);
            *reinterpret_cast<float4*>(&sm[UHB + n * PAD + u4 * 4]) = make_float4(c0, c1, c2, c3);
        }
    }
    __syncthreads();

    // ================= Dynamic routing (3 iterations) =================
    // Notes: initial logits b=1 drop out of softmax -> iter 0 uses uniform c=1/N.
    // c[] stores UNNORMALIZED exp(a - max); 1/S is folded into the s reduction.
    for (int it = 0; it < 3; ++it) {
        // ---- Phase A: per-thread partial s[u] = sum_n c[n] * u_hat[n][u] ----
        {
            const int u4 = t & 3;
            const int gg = t >> 2;
            float p0[4] = {0.f, 0.f, 0.f, 0.f};
            float p1[4] = {0.f, 0.f, 0.f, 0.f};
            for (int k = 0; k < 9; ++k) {
                const int n = gg + (k << 7);
                float cw0, cw1;
                if (it == 0) { cw0 = 1.0f; cw1 = 1.0f; }
                else { cw0 = sm[CC_OFF + n]; cw1 = sm[CC_OFF + NN + n]; }
                float4 u0 = *reinterpret_cast<const float4*>(&sm[      n * PAD + u4 * 4]);
                float4 u1 = *reinterpret_cast<const float4*>(&sm[UHB + n * PAD + u4 * 4]);
                p0[0] += cw0 * u0.x; p0[1] += cw0 * u0.y; p0[2] += cw0 * u0.z; p0[3] += cw0 * u0.w;
                p1[0] += cw1 * u1.x; p1[1] += cw1 * u1.y; p1[2] += cw1 * u1.z; p1[3] += cw1 * u1.w;
            }
            // butterfly over the 8 gg values within this warp (same u4)
            #pragma unroll
            for (int off = 4; off <= 16; off <<= 1) {
                #pragma unroll
                for (int j = 0; j < 4; ++j) {
                    p0[j] += __shfl_xor_sync(0xffffffffu, p0[j], off);
                    p1[j] += __shfl_xor_sync(0xffffffffu, p1[j], off);
                }
            }
            if (lane < 4) {
                #pragma unroll
                for (int j = 0; j < 4; ++j) {
                    sm[RED_OFF + (0 * 16 + warp) * 16 + lane * 4 + j] = p0[j];
                    sm[RED_OFF + (1 * 16 + warp) * 16 + lane * 4 + j] = p1[j];
                }
            }
        }
        __syncthreads();

        // ---- Phase B: warp 0 finalizes s, applies squash -> v ----
        if (warp == 0) {
            const int q = lane >> 4;
            const int u = lane & 15;
            float s = 0.f;
            #pragma unroll
            for (int w = 0; w < 16; ++w) s += sm[RED_OFF + (q * 16 + w) * 16 + u];
            const float inv = (it == 0) ? (1.0f / (float)NN) : (1.0f / sm[MS_OFF + 2 + q]);
            s *= inv;
            float sq = s * s;
            #pragma unroll
            for (int off = 1; off <= 8; off <<= 1) sq += __shfl_xor_sync(0xffffffffu, sq, off);
            const float scale = sq / ((1.0f + sq) * sqrtf(sq + 1e-9f));
            const float v = scale * s;
            sm[VS_OFF + lane] = v;
            if (it == 2) out[((size_t)(b0 + q) * NC + cc) * NU + u] = v;
        }
        if (it == 2) break;
        __syncthreads();

        // ---- Phase C1: agreement update a[n] += u_hat[n]·v ; track local max ----
        float lmax0 = -FLT_MAX, lmax1 = -FLT_MAX;
        {
            float vr0[16], vr1[16];
            #pragma unroll
            for (int j = 0; j < 4; ++j) {
                float4 a = *reinterpret_cast<const float4*>(&sm[VS_OFF + j * 4]);
                vr0[j * 4 + 0] = a.x; vr0[j * 4 + 1] = a.y; vr0[j * 4 + 2] = a.z; vr0[j * 4 + 3] = a.w;
                float4 b = *reinterpret_cast<const float4*>(&sm[VS_OFF + 16 + j * 4]);
                vr1[j * 4 + 0] = b.x; vr1[j * 4 + 1] = b.y; vr1[j * 4 + 2] = b.z; vr1[j * 4 + 3] = b.w;
            }
            for (int n = t; n < NN; n += TPB) {
                float d0 = 0.f, d1 = 0.f;
                #pragma unroll
                for (int j = 0; j < 4; ++j) {
                    float4 u0 = *reinterpret_cast<const float4*>(&sm[      n * PAD + j * 4]);
                    float4 u1 = *reinterpret_cast<const float4*>(&sm[UHB + n * PAD + j * 4]);
                    d0 += u0.x * vr0[j*4+0] + u0.y * vr0[j*4+1] + u0.z * vr0[j*4+2] + u0.w * vr0[j*4+3];
                    d1 += u1.x * vr1[j*4+0] + u1.y * vr1[j*4+1] + u1.z * vr1[j*4+2] + u1.w * vr1[j*4+3];
                }
                float av0 = (it == 0) ? d0 : (sm[A_OFF + n]      + d0);
                float av1 = (it == 0) ? d1 : (sm[A_OFF + NN + n] + d1);
                sm[A_OFF + n]      = av0;
                sm[A_OFF + NN + n] = av1;
                lmax0 = fmaxf(lmax0, av0);
                lmax1 = fmaxf(lmax1, av1);
            }
            #pragma unroll
            for (int off = 1; off <= 16; off <<= 1) {
                lmax0 = fmaxf(lmax0, __shfl_xor_sync(0xffffffffu, lmax0, off));
                lmax1 = fmaxf(lmax1, __shfl_xor_sync(0xffffffffu, lmax1, off));
            }
            if (lane == 0) { sm[WRED_OFF + warp] = lmax0; sm[WRED_OFF + 16 + warp] = lmax1; }
        }
        __syncthreads();

        // ---- Phase C2: finalize block max per batch ----
        if (warp == 0) {
            float m = sm[WRED_OFF + lane];   // lanes 0..15 = q0 warps, 16..31 = q1
            #pragma unroll
            for (int off = 1; off <= 8; off <<= 1) m = fmaxf(m, __shfl_xor_sync(0xffffffffu, m, off));
            if ((lane & 15) == 0) sm[MS_OFF + (lane >> 4)] = m;
        }
        __syncthreads();

        // ---- Phase C3: c[n] = exp(a[n]-m) (unnormalized), accumulate S ----
        {
            const float m0 = sm[MS_OFF + 0];
            const float m1 = sm[MS_OFF + 1];
            float ls0 = 0.f, ls1 = 0.f;
            for (int n = t; n < NN; n += TPB) {
                float e0 = __expf(sm[A_OFF + n]      - m0);
                float e1 = __expf(sm[A_OFF + NN + n] - m1);
                sm[CC_OFF + n]      = e0;  ls0 += e0;
                sm[CC_OFF + NN + n] = e1;  ls1 += e1;
            }
            #pragma unroll
            for (int off = 1; off <= 16; off <<= 1) {
                ls0 += __shfl_xor_sync(0xffffffffu, ls0, off);
                ls1 += __shfl_xor_sync(0xffffffffu, ls1, off);
            }
            if (lane == 0) { sm[WRED_OFF + warp] = ls0; sm[WRED_OFF + 16 + warp] = ls1; }
        }
        __syncthreads();
        if (warp == 0) {
            float s = sm[WRED_OFF + lane];
            #pragma unroll
            for (int off = 1; off <= 8; off <<= 1) s += __shfl_xor_sync(0xffffffffu, s, off);
            if ((lane & 15) == 0) sm[MS_OFF + 2 + (lane >> 4)] = s;   // S[q]
        }
        __syncthreads();
    }
}

extern "C" void kernel_launch(void* const* d_in, const int* in_sizes, int n_in,
                              void* d_out, int out_size)
{
    // inputs: (256,1152,8)=2359296 floats ; W: (10,1152,8,16)=1474560 floats
    const float* inp = (const float*)d_in[0];
    const float* W   = (const float*)d_in[1];
    if (n_in >= 2 && in_sizes[0] == NC * NN * DIN * NU && in_sizes[1] == NB * NN * DIN) {
        // defensive: swap if metadata order differs
        const float* tmp = inp; inp = W; W = tmp;
    }
    float* out = (float*)d_out;

    const int smem_bytes = SMEM_FLOATS * (int)sizeof(float);   // 205072
    cudaFuncSetAttribute(caps_routing_kernel,
                         cudaFuncAttributeMaxDynamicSharedMemorySize, smem_bytes);

    dim3 grid(NC, NB / 2);   // (10, 128) -> 1280 CTAs
    caps_routing_kernel<<<grid, TPB, smem_bytes>>>(inp, W, out);
}

// round 4
// speedup vs baseline: 1.3529x; 1.3529x over previous
#include <cuda_runtime.h>
#include <cfloat>

// Problem constants
#define NB    256     // batch
#define NN    1152    // input capsules
#define DIN   8       // input capsule dim
#define NC    10      // output capsules
#define NU    16      // output capsule dim
#define TPB   512
#define KROWS 9       // rows per thread (1152 / 128 gg-groups)

// Tiny static shared: reduction scratch only (u_hat lives in registers).
__global__ __launch_bounds__(TPB, 1)
void caps_routing_reg_kernel(const float* __restrict__ inp,
                             const float* __restrict__ W,
                             float* __restrict__ out)
{
    __shared__ float RED[16 * 32];   // [warp][batch(2)][u(16)] s-partials
    __shared__ float WRED[32];       // per-warp scalar partials [2][16]
    __shared__ float MS[4];          // m0, m1, S0, S1
    __shared__ float VS[32];         // v[2][16]

    const int t    = threadIdx.x;
    const int lane = t & 31;
    const int warp = t >> 5;
    const int u4   = t & 3;          // which 4-float u chunk this thread owns
    const int gg   = t >> 2;         // row group 0..127
    const int cc   = blockIdx.x;     // output capsule
    const int b0   = blockIdx.y << 1;

    // Persistent per-thread state: u_hat[9 rows][4 u] for both batches + logits
    float u0[KROWS][4], u1[KROWS][4];
    float a0[KROWS], a1[KROWS];

    // ================= Phase 0: u_hat into REGISTERS =================
    {
        const float* Wc = W + (size_t)cc * (NN * DIN * NU);
        #pragma unroll
        for (int k = 0; k < KROWS; ++k) {
            const int n = gg + (k << 7);
            const float4* ip0 = reinterpret_cast<const float4*>(inp + ((size_t)b0       * NN + n) * DIN);
            const float4* ip1 = reinterpret_cast<const float4*>(inp + ((size_t)(b0 + 1) * NN + n) * DIN);
            float4 x0 = ip0[0], x1 = ip0[1];
            float4 y0 = ip1[0], y1 = ip1[1];
            float in0[8] = {x0.x, x0.y, x0.z, x0.w, x1.x, x1.y, x1.z, x1.w};
            float in1[8] = {y0.x, y0.y, y0.z, y0.w, y1.x, y1.y, y1.z, y1.w};
            const float4* wp = reinterpret_cast<const float4*>(Wc + (size_t)n * (DIN * NU)) + u4;
            float r0 = 0.f, r1 = 0.f, r2 = 0.f, r3 = 0.f;
            float q0 = 0.f, q1 = 0.f, q2 = 0.f, q3 = 0.f;
            #pragma unroll
            for (int i = 0; i < 8; ++i) {
                float4 w = wp[i * 4];          // W[c][n][i][u4*4 .. +3]
                r0 += in0[i] * w.x;  r1 += in0[i] * w.y;
                r2 += in0[i] * w.z;  r3 += in0[i] * w.w;
                q0 += in1[i] * w.x;  q1 += in1[i] * w.y;
                q2 += in1[i] * w.z;  q3 += in1[i] * w.w;
            }
            u0[k][0] = r0; u0[k][1] = r1; u0[k][2] = r2; u0[k][3] = r3;
            u1[k][0] = q0; u1[k][1] = q1; u1[k][2] = q2; u1[k][3] = q3;
        }
    }
    // no sync needed: everything so far is thread-private

    // ================= Dynamic routing (3 iterations) =================
    // Initial logits b=1 drop out of softmax (iter 0: uniform c = 1/N).
    // Coupling weights recomputed as exp(a-m); 1/S folded into phase B.
    for (int it = 0; it < 3; ++it) {
        // ---- Phase A: partial s[u] = sum_n exp(a[n]-m) * u_hat[n][u] ----
        {
            float m0v = 0.f, m1v = 0.f;
            if (it > 0) { m0v = MS[0]; m1v = MS[1]; }
            float s0[4] = {0.f, 0.f, 0.f, 0.f};
            float s1[4] = {0.f, 0.f, 0.f, 0.f};
            #pragma unroll
            for (int k = 0; k < KROWS; ++k) {
                const float cw0 = (it == 0) ? 1.0f : __expf(a0[k] - m0v);
                const float cw1 = (it == 0) ? 1.0f : __expf(a1[k] - m1v);
                #pragma unroll
                for (int j = 0; j < 4; ++j) {
                    s0[j] += cw0 * u0[k][j];
                    s1[j] += cw1 * u1[k][j];
                }
            }
            // butterfly over the 8 gg groups in this warp (same u4)
            #pragma unroll
            for (int off = 4; off <= 16; off <<= 1) {
                #pragma unroll
                for (int j = 0; j < 4; ++j) {
                    s0[j] += __shfl_xor_sync(0xffffffffu, s0[j], off);
                    s1[j] += __shfl_xor_sync(0xffffffffu, s1[j], off);
                }
            }
            if (lane < 4) {   // lane == u4 for lanes 0..3; holds warp sum for its u4
                *reinterpret_cast<float4*>(&RED[warp * 32 +      u4 * 4]) = make_float4(s0[0], s0[1], s0[2], s0[3]);
                *reinterpret_cast<float4*>(&RED[warp * 32 + 16 + u4 * 4]) = make_float4(s1[0], s1[1], s1[2], s1[3]);
            }
        }
        __syncthreads();

        // ---- Phase B: warp 0 finalizes s, applies squash -> v ----
        if (warp == 0) {
            const int q = lane >> 4;     // batch within pair
            const int u = lane & 15;
            float s = 0.f;
            #pragma unroll
            for (int w = 0; w < 16; ++w) s += RED[w * 32 + lane];   // = [w][q][u], conflict-free
            const float inv = (it == 0) ? (1.0f / (float)NN) : (1.0f / MS[2 + q]);
            s *= inv;
            float sq = s * s;
            #pragma unroll
            for (int off = 1; off <= 8; off <<= 1) sq += __shfl_xor_sync(0xffffffffu, sq, off);
            const float scale = sq / ((1.0f + sq) * sqrtf(sq + 1e-9f));
            const float v = scale * s;
            VS[lane] = v;
            if (it == 2) out[((size_t)(b0 + q) * NC + cc) * NU + u] = v;
        }
        if (it == 2) return;
        __syncthreads();

        // ---- Phase C1: agreement a[n] += u_hat[n]·v ; track max ----
        float lmax0 = -FLT_MAX, lmax1 = -FLT_MAX;
        {
            const float4 v0 = *reinterpret_cast<const float4*>(&VS[u4 * 4]);
            const float4 v1 = *reinterpret_cast<const float4*>(&VS[16 + u4 * 4]);
            #pragma unroll
            for (int k = 0; k < KROWS; ++k) {
                float d0 = u0[k][0] * v0.x + u0[k][1] * v0.y + u0[k][2] * v0.z + u0[k][3] * v0.w;
                float d1 = u1[k][0] * v1.x + u1[k][1] * v1.y + u1[k][2] * v1.z + u1[k][3] * v1.w;
                // reduce over the 4 u-chunks within the quad
                d0 += __shfl_xor_sync(0xffffffffu, d0, 1);
                d0 += __shfl_xor_sync(0xffffffffu, d0, 2);
                d1 += __shfl_xor_sync(0xffffffffu, d1, 1);
                d1 += __shfl_xor_sync(0xffffffffu, d1, 2);
                a0[k] = (it == 0) ? d0 : (a0[k] + d0);
                a1[k] = (it == 0) ? d1 : (a1[k] + d1);
                lmax0 = fmaxf(lmax0, a0[k]);
                lmax1 = fmaxf(lmax1, a1[k]);
            }
            #pragma unroll
            for (int off = 1; off <= 16; off <<= 1) {
                lmax0 = fmaxf(lmax0, __shfl_xor_sync(0xffffffffu, lmax0, off));
                lmax1 = fmaxf(lmax1, __shfl_xor_sync(0xffffffffu, lmax1, off));
            }
            if (lane == 0) { WRED[warp] = lmax0; WRED[16 + warp] = lmax1; }
        }
        __syncthreads();

        // ---- Phase C2: block max per batch ----
        if (warp == 0) {
            float m = WRED[lane];     // lanes 0..15 = batch0 warps, 16..31 = batch1
            #pragma unroll
            for (int off = 1; off <= 8; off <<= 1) m = fmaxf(m, __shfl_xor_sync(0xffffffffu, m, off));
            if ((lane & 15) == 0) MS[lane >> 4] = m;
        }
        __syncthreads();

        // ---- Phase C3: S = sum exp(a-m)  (quad redundancy corrected by x0.25) ----
        {
            const float mm0 = MS[0];
            const float mm1 = MS[1];
            float ls0 = 0.f, ls1 = 0.f;
            #pragma unroll
            for (int k = 0; k < KROWS; ++k) {
                ls0 += __expf(a0[k] - mm0);
                ls1 += __expf(a1[k] - mm1);
            }
            #pragma unroll
            for (int off = 1; off <= 16; off <<= 1) {
                ls0 += __shfl_xor_sync(0xffffffffu, ls0, off);
                ls1 += __shfl_xor_sync(0xffffffffu, ls1, off);
            }
            if (lane == 0) { WRED[warp] = ls0; WRED[16 + warp] = ls1; }
        }
        __syncthreads();
        if (warp == 0) {
            float s = WRED[lane];
            #pragma unroll
            for (int off = 1; off <= 8; off <<= 1) s += __shfl_xor_sync(0xffffffffu, s, off);
            if ((lane & 15) == 0) MS[2 + (lane >> 4)] = s * 0.25f;   // undo 4x quad redundancy
        }
        __syncthreads();
    }
}

extern "C" void kernel_launch(void* const* d_in, const int* in_sizes, int n_in,
                              void* d_out, int out_size)
{
    const float* inp = (const float*)d_in[0];
    const float* W   = (const float*)d_in[1];
    if (n_in >= 2 && in_sizes[0] == NC * NN * DIN * NU && in_sizes[1] == NB * NN * DIN) {
        const float* tmp = inp; inp = W; W = tmp;   // defensive order swap
    }
    float* out = (float*)d_out;

    dim3 grid(NC, NB / 2);   // 10 x 128 = 1280 CTAs, one batch-pair each
    caps_routing_reg_kernel<<<grid, TPB>>>(inp, W, out);
}